// round 12
// baseline (speedup 1.0000x reference)
#include <cuda_runtime.h>

#define B_TOT 8192
#define N_NET 722
#define CAMD  10
#define IND   11
#define HD    10
#define LODD  6
#define GN    4     // nets per block (n uniform PER WARP -> weight broadcast kept)
#define ROWS  128   // batch rows per block

using u64 = unsigned long long;

static __device__ __forceinline__ u64 pk2(float a, float b) {
    u64 r; asm("mov.b64 %0, {%1, %2};" : "=l"(r) : "f"(a), "f"(b)); return r;
}
static __device__ __forceinline__ void unpk2(u64 v, float& a, float& b) {
    asm("mov.b64 {%0, %1}, %2;" : "=f"(a), "=f"(b) : "l"(v));
}
// Packed 2-wide fp32 FMA (Blackwell FFMA2) — only reachable via PTX.
static __device__ __forceinline__ u64 ffma2(u64 a, u64 b, u64 c) {
    u64 d; asm("fma.rn.f32x2 %0, %1, %2, %3;" : "=l"(d) : "l"(a), "l"(b), "l"(c)); return d;
}
static __device__ __forceinline__ u64 relu2(u64 v) {
    float a, b; unpk2(v, a, b);
    a = fmaxf(a, 0.0f); b = fmaxf(b, 0.0f);
    return pk2(a, b);
}
// 16-byte broadcast shared load: two duplicated weights -> feeds two FFMA2s.
static __device__ __forceinline__ void lds2(const u64* p, u64& w0, u64& w1) {
    asm("ld.shared.v2.u64 {%0, %1}, [%2];"
        : "=l"(w0), "=l"(w1) : "l"(__cvta_generic_to_shared(p)));
}

// R11 structure (per-warp net -> broadcast weight LDS; smem-tiled coalesced
// stores; staged prior) with ONE change: each lane's f32x2 pair now holds
// INTERLEAVED rows (L, L+32) instead of adjacent rows (2L, 2L+1). Camera
// float2 loads then have 40B lane stride -> 10 lines/inst instead of 20,
// halving the dominant remaining L1tex term (camera: ~200 -> ~100 wf/warp).
__global__ __launch_bounds__(256, 3) void mlp_kernel(
    const float* __restrict__ prior,  // [B, N]
    const float* __restrict__ cam,    // [B, CAM]
    const float* __restrict__ W1,     // [N, IN, H]
    const float* __restrict__ b1,     // [N, H]
    const float* __restrict__ W2,     // [N, H, H]
    const float* __restrict__ b2,     // [N, H]
    const float* __restrict__ W3,     // [N, H, LOD]
    const float* __restrict__ b3,     // [N, LOD]
    float* __restrict__ out)          // [B, N, LOD]
{
    __shared__ __align__(16) u64 s_w1[GN][IND * HD];
    __shared__ __align__(16) u64 s_b1[GN][HD];
    __shared__ __align__(16) u64 s_w2[GN][HD * HD];
    __shared__ __align__(16) u64 s_b2[GN][HD];
    __shared__ __align__(16) u64 s_w3[GN][HD * LODD];
    __shared__ __align__(16) u64 s_b3[GN][LODD + 2];
    __shared__ float s_pr[ROWS][GN + 1];        // prior stage, stride 5 words
    __shared__ float s_out[ROWS * 25];          // row stride 25 words (24 used)

    const int tid   = threadIdx.x;
    const int nbase = blockIdx.x * GN;
    const int bbase = blockIdx.y * ROWS;

    // ---- Stage 4 nets' weights, duplicated (w,w) ----
    for (int idx = tid; idx < GN * IND * HD; idx += 256) {
        int j = idx / (IND * HD), i = idx - j * (IND * HD);
        int nj = min(nbase + j, N_NET - 1);
        float v = W1[nj * IND * HD + i]; s_w1[j][i] = pk2(v, v);
    }
    for (int idx = tid; idx < GN * HD * HD; idx += 256) {
        int j = idx / (HD * HD), i = idx - j * (HD * HD);
        int nj = min(nbase + j, N_NET - 1);
        float v = W2[nj * HD * HD + i]; s_w2[j][i] = pk2(v, v);
    }
    for (int idx = tid; idx < GN * HD * LODD; idx += 256) {
        int j = idx / (HD * LODD), i = idx - j * (HD * LODD);
        int nj = min(nbase + j, N_NET - 1);
        float v = W3[nj * HD * LODD + i]; s_w3[j][i] = pk2(v, v);
    }
    if (tid < GN * HD) {
        int j = tid / HD, i = tid - j * HD;
        int nj = min(nbase + j, N_NET - 1);
        float v = b1[nj * HD + i]; s_b1[j][i] = pk2(v, v);
        v       = b2[nj * HD + i]; s_b2[j][i] = pk2(v, v);
    }
    if (tid < GN * LODD) {
        int j = tid / LODD, i = tid - j * LODD;
        int nj = min(nbase + j, N_NET - 1);
        float v = b3[nj * LODD + i]; s_b3[j][i] = pk2(v, v);
    }

    // ---- Stage prior[bbase..+127][nbase..+3] (coalesced 16B per row) ----
    for (int idx = tid; idx < ROWS * GN; idx += 256) {
        int r = idx >> 2, nt = idx & 3;
        int nj = min(nbase + nt, N_NET - 1);
        s_pr[r][nt] = prior[(size_t)(bbase + r) * N_NET + nj];
    }
    __syncthreads();

    const int w  = tid >> 5;
    const int L  = tid & 31;
    const int ns = w & (GN - 1);   // net uniform per warp -> broadcast LDS
    const int rg = w >> 2;         // row group (64 rows per warp)
    const int ra = rg * 64 + L;        // interleaved row pair: (ra, rb=ra+32)
    const int rb = ra + 32;
    const int ba = bbase + ra;
    const int bb = bbase + rb;

    // ---- Inputs: pair = rows (ra, rb); camera lanes at 40B stride = 10 lines/inst ----
    u64 x[IND];
    x[0] = pk2(s_pr[ra][ns], s_pr[rb][ns]);
    {
        const float2* ca = reinterpret_cast<const float2*>(cam + (size_t)ba * CAMD);
        const float2* cb = reinterpret_cast<const float2*>(cam + (size_t)bb * CAMD);
#pragma unroll
        for (int c = 0; c < 5; c++) {
            float2 va = ca[c], vb = cb[c];
            x[1 + 2 * c] = pk2(va.x, vb.x);
            x[2 + 2 * c] = pk2(va.y, vb.y);
        }
    }

    // ---- Layer 1: [IN=11] -> [H=10], ReLU ----
    u64 h1[HD];
#pragma unroll
    for (int h = 0; h < HD; h += 2) lds2(&s_b1[ns][h], h1[h], h1[h + 1]);
#pragma unroll
    for (int i = 0; i < IND; i++) {
#pragma unroll
        for (int h = 0; h < HD; h += 2) {
            u64 w0, w1v; lds2(&s_w1[ns][i * HD + h], w0, w1v);
            h1[h]     = ffma2(x[i], w0,  h1[h]);
            h1[h + 1] = ffma2(x[i], w1v, h1[h + 1]);
        }
    }
#pragma unroll
    for (int h = 0; h < HD; h++) h1[h] = relu2(h1[h]);

    // ---- Layer 2: [H=10] -> [H=10], ReLU ----
    u64 h2[HD];
#pragma unroll
    for (int k = 0; k < HD; k += 2) lds2(&s_b2[ns][k], h2[k], h2[k + 1]);
#pragma unroll
    for (int h = 0; h < HD; h++) {
#pragma unroll
        for (int k = 0; k < HD; k += 2) {
            u64 w0, w1v; lds2(&s_w2[ns][h * HD + k], w0, w1v);
            h2[k]     = ffma2(h1[h], w0,  h2[k]);
            h2[k + 1] = ffma2(h1[h], w1v, h2[k + 1]);
        }
    }
#pragma unroll
    for (int k = 0; k < HD; k++) h2[k] = relu2(h2[k]);

    // ---- Layer 3: [H=10] -> [LOD=6] ----
    u64 o[LODD];
#pragma unroll
    for (int l = 0; l < LODD; l += 2) lds2(&s_b3[ns][l], o[l], o[l + 1]);
#pragma unroll
    for (int h = 0; h < HD; h++) {
#pragma unroll
        for (int l = 0; l < LODD; l += 2) {
            u64 w0, w1v; lds2(&s_w3[ns][h * LODD + l], w0, w1v);
            o[l]     = ffma2(h2[h], w0,  o[l]);
            o[l + 1] = ffma2(h2[h], w1v, o[l + 1]);
        }
    }

    // ---- Deposit into smem tile: s_out[r*25 + ns*6 + c] ----
    {
        float oa[LODD], ob[LODD];
#pragma unroll
        for (int l = 0; l < LODD; l++) unpk2(o[l], oa[l], ob[l]);
        float* pa = &s_out[ra * 25 + ns * 6];
        float* pb = &s_out[rb * 25 + ns * 6];
#pragma unroll
        for (int l = 0; l < LODD; l++) { pa[l] = oa[l]; pb[l] = ob[l]; }
    }
    __syncthreads();

    // ---- Cooperative store: 128 rows x 96B contiguous chunks, STG.128 ----
    // Chunk base (b*722+nbase)*24B: b*722 even, nbase%4==0 -> 48k -> 16B aligned.
    const int valid_bytes = min(GN, N_NET - nbase) * 24;   // 96 or 48 (722%4==2)
#pragma unroll
    for (int u = tid; u < ROWS * 6; u += 256) {
        int r = u / 6, s = u - r * 6;
        if (s * 16 < valid_bytes) {
            const float* src = &s_out[r * 25 + s * 4];
            float4 v = make_float4(src[0], src[1], src[2], src[3]);
            float* dst = out + ((size_t)(bbase + r) * N_NET + nbase) * LODD + s * 4;
            *reinterpret_cast<float4*>(dst) = v;
        }
    }
}

extern "C" void kernel_launch(void* const* d_in, const int* in_sizes, int n_in,
                              void* d_out, int out_size) {
    const float* prior = (const float*)d_in[0];
    const float* cam   = (const float*)d_in[1];
    const float* W1    = (const float*)d_in[2];
    const float* b1    = (const float*)d_in[3];
    const float* W2    = (const float*)d_in[4];
    const float* b2    = (const float*)d_in[5];
    const float* W3    = (const float*)d_in[6];
    const float* b3    = (const float*)d_in[7];
    float* out = (float*)d_out;

    dim3 grid((N_NET + GN - 1) / GN, B_TOT / ROWS);   // 181 x 64
    mlp_kernel<<<grid, 256>>>(prior, cam, W1, b1, W2, b2, W3, b3, out);
}

// round 13
// speedup vs baseline: 1.4170x; 1.4170x over previous
#include <cuda_runtime.h>

#define B_TOT 8192
#define N_NET 722
#define CAMD  10
#define IND   11
#define HD    10
#define LODD  6
#define GN    4     // nets per block (n uniform PER WARP -> weight broadcast kept)
#define ROWS  128   // batch rows per block

using u64 = unsigned long long;

static __device__ __forceinline__ u64 pk2(float a, float b) {
    u64 r; asm("mov.b64 %0, {%1, %2};" : "=l"(r) : "f"(a), "f"(b)); return r;
}
static __device__ __forceinline__ void unpk2(u64 v, float& a, float& b) {
    asm("mov.b64 {%0, %1}, %2;" : "=f"(a), "=f"(b) : "l"(v));
}
// Packed 2-wide fp32 FMA (Blackwell FFMA2) — only reachable via PTX.
static __device__ __forceinline__ u64 ffma2(u64 a, u64 b, u64 c) {
    u64 d; asm("fma.rn.f32x2 %0, %1, %2, %3;" : "=l"(d) : "l"(a), "l"(b), "l"(c)); return d;
}
static __device__ __forceinline__ u64 relu2(u64 v) {
    float a, b; unpk2(v, a, b);
    a = fmaxf(a, 0.0f); b = fmaxf(b, 0.0f);
    return pk2(a, b);
}
// 16-byte broadcast shared load: two duplicated weights -> feeds two FFMA2s.
static __device__ __forceinline__ void lds2(const u64* p, u64& w0, u64& w1) {
    asm("ld.shared.v2.u64 {%0, %1}, [%2];"
        : "=l"(w0), "=l"(w1) : "l"(__cvta_generic_to_shared(p)));
}

// EXACT R11 structure (best: 170.9us) — per-warp net (broadcast weight LDS),
// adjacent row pair (2L, 2L+1) per lane, smem-tiled coalesced stores, staged
// prior — with ONE change: the thread's two camera rows are 80B CONTIGUOUS,
// so the 10x LDG.64 camera loads become 5x LDG.128 over byte-identical data
// (same 20-line footprint, half the instructions -> camera wavefronts halve).
// R12's interleaved (L, L+32) mapping regressed 40% -> row mapping reverted.
__global__ __launch_bounds__(256, 3) void mlp_kernel(
    const float* __restrict__ prior,  // [B, N]
    const float* __restrict__ cam,    // [B, CAM]
    const float* __restrict__ W1,     // [N, IN, H]
    const float* __restrict__ b1,     // [N, H]
    const float* __restrict__ W2,     // [N, H, H]
    const float* __restrict__ b2,     // [N, H]
    const float* __restrict__ W3,     // [N, H, LOD]
    const float* __restrict__ b3,     // [N, LOD]
    float* __restrict__ out)          // [B, N, LOD]
{
    __shared__ __align__(16) u64 s_w1[GN][IND * HD];
    __shared__ __align__(16) u64 s_b1[GN][HD];
    __shared__ __align__(16) u64 s_w2[GN][HD * HD];
    __shared__ __align__(16) u64 s_b2[GN][HD];
    __shared__ __align__(16) u64 s_w3[GN][HD * LODD];
    __shared__ __align__(16) u64 s_b3[GN][LODD + 2];
    __shared__ float s_pr[ROWS][GN + 1];        // prior stage, pad->deg-2 banks
    __shared__ float s_out[ROWS * 25];          // row stride 25 words (24 used)

    const int tid   = threadIdx.x;
    const int nbase = blockIdx.x * GN;
    const int bbase = blockIdx.y * ROWS;

    // ---- Stage 4 nets' weights, duplicated (w,w) ----
    for (int idx = tid; idx < GN * IND * HD; idx += 256) {
        int j = idx / (IND * HD), i = idx - j * (IND * HD);
        int nj = min(nbase + j, N_NET - 1);
        float v = W1[nj * IND * HD + i]; s_w1[j][i] = pk2(v, v);
    }
    for (int idx = tid; idx < GN * HD * HD; idx += 256) {
        int j = idx / (HD * HD), i = idx - j * (HD * HD);
        int nj = min(nbase + j, N_NET - 1);
        float v = W2[nj * HD * HD + i]; s_w2[j][i] = pk2(v, v);
    }
    for (int idx = tid; idx < GN * HD * LODD; idx += 256) {
        int j = idx / (HD * LODD), i = idx - j * (HD * LODD);
        int nj = min(nbase + j, N_NET - 1);
        float v = W3[nj * HD * LODD + i]; s_w3[j][i] = pk2(v, v);
    }
    if (tid < GN * HD) {
        int j = tid / HD, i = tid - j * HD;
        int nj = min(nbase + j, N_NET - 1);
        float v = b1[nj * HD + i]; s_b1[j][i] = pk2(v, v);
        v       = b2[nj * HD + i]; s_b2[j][i] = pk2(v, v);
    }
    if (tid < GN * LODD) {
        int j = tid / LODD, i = tid - j * LODD;
        int nj = min(nbase + j, N_NET - 1);
        float v = b3[nj * LODD + i]; s_b3[j][i] = pk2(v, v);
    }

    // ---- Stage prior[bbase..+127][nbase..+3] (coalesced 16B per row) ----
    for (int idx = tid; idx < ROWS * GN; idx += 256) {
        int r = idx >> 2, nt = idx & 3;
        int nj = min(nbase + nt, N_NET - 1);
        s_pr[r][nt] = prior[(size_t)(bbase + r) * N_NET + nj];
    }
    __syncthreads();

    const int w  = tid >> 5;
    const int L  = tid & 31;
    const int ns = w & (GN - 1);   // net uniform per warp -> broadcast LDS
    const int rg = w >> 2;         // row group (2 per net)
    const int r0 = rg * 64 + L * 2;    // adjacent row pair (R11 mapping)
    const int b0 = bbase + r0;

    // ---- Inputs: rows (b0, b0+1) are 80B contiguous in cam -> 5x LDG.128 ----
    // byte offset = b0*40, b0 even -> 16B aligned.
    u64 x[IND];
    x[0] = pk2(s_pr[r0][ns], s_pr[r0 + 1][ns]);
    {
        const float4* cp = reinterpret_cast<const float4*>(cam + (size_t)b0 * CAMD);
        float4 v0 = cp[0], v1 = cp[1], v2 = cp[2], v3 = cp[3], v4 = cp[4];
        // rowA = [v0.x..v1.w, v2.x, v2.y], rowB = [v2.z, v2.w, v3.x..v4.w]
        x[1]  = pk2(v0.x, v2.z);
        x[2]  = pk2(v0.y, v2.w);
        x[3]  = pk2(v0.z, v3.x);
        x[4]  = pk2(v0.w, v3.y);
        x[5]  = pk2(v1.x, v3.z);
        x[6]  = pk2(v1.y, v3.w);
        x[7]  = pk2(v1.z, v4.x);
        x[8]  = pk2(v1.w, v4.y);
        x[9]  = pk2(v2.x, v4.z);
        x[10] = pk2(v2.y, v4.w);
    }

    // ---- Layer 1: [IN=11] -> [H=10], ReLU ----
    u64 h1[HD];
#pragma unroll
    for (int h = 0; h < HD; h += 2) lds2(&s_b1[ns][h], h1[h], h1[h + 1]);
#pragma unroll
    for (int i = 0; i < IND; i++) {
#pragma unroll
        for (int h = 0; h < HD; h += 2) {
            u64 w0, w1v; lds2(&s_w1[ns][i * HD + h], w0, w1v);
            h1[h]     = ffma2(x[i], w0,  h1[h]);
            h1[h + 1] = ffma2(x[i], w1v, h1[h + 1]);
        }
    }
#pragma unroll
    for (int h = 0; h < HD; h++) h1[h] = relu2(h1[h]);

    // ---- Layer 2: [H=10] -> [H=10], ReLU ----
    u64 h2[HD];
#pragma unroll
    for (int k = 0; k < HD; k += 2) lds2(&s_b2[ns][k], h2[k], h2[k + 1]);
#pragma unroll
    for (int h = 0; h < HD; h++) {
#pragma unroll
        for (int k = 0; k < HD; k += 2) {
            u64 w0, w1v; lds2(&s_w2[ns][h * HD + k], w0, w1v);
            h2[k]     = ffma2(h1[h], w0,  h2[k]);
            h2[k + 1] = ffma2(h1[h], w1v, h2[k + 1]);
        }
    }
#pragma unroll
    for (int k = 0; k < HD; k++) h2[k] = relu2(h2[k]);

    // ---- Layer 3: [H=10] -> [LOD=6] ----
    u64 o[LODD];
#pragma unroll
    for (int l = 0; l < LODD; l += 2) lds2(&s_b3[ns][l], o[l], o[l + 1]);
#pragma unroll
    for (int h = 0; h < HD; h++) {
#pragma unroll
        for (int l = 0; l < LODD; l += 2) {
            u64 w0, w1v; lds2(&s_w3[ns][h * LODD + l], w0, w1v);
            o[l]     = ffma2(h2[h], w0,  o[l]);
            o[l + 1] = ffma2(h2[h], w1v, o[l + 1]);
        }
    }

    // ---- Deposit into smem tile: s_out[r*25 + ns*6 + c] ----
    {
        float oa[LODD], ob[LODD];
#pragma unroll
        for (int l = 0; l < LODD; l++) unpk2(o[l], oa[l], ob[l]);
        float* pa = &s_out[r0 * 25 + ns * 6];
        float* pb = pa + 25;
#pragma unroll
        for (int l = 0; l < LODD; l++) { pa[l] = oa[l]; pb[l] = ob[l]; }
    }
    __syncthreads();

    // ---- Cooperative store: 128 rows x 96B contiguous chunks, STG.128 ----
    // Chunk base (b*722+nbase)*24B: b*722 even, nbase%4==0 -> 48k -> 16B aligned.
    const int valid_bytes = min(GN, N_NET - nbase) * 24;   // 96 or 48 (722%4==2)
#pragma unroll
    for (int u = tid; u < ROWS * 6; u += 256) {
        int r = u / 6, s = u - r * 6;
        if (s * 16 < valid_bytes) {
            const float* src = &s_out[r * 25 + s * 4];
            float4 v = make_float4(src[0], src[1], src[2], src[3]);
            float* dst = out + ((size_t)(bbase + r) * N_NET + nbase) * LODD + s * 4;
            *reinterpret_cast<float4*>(dst) = v;
        }
    }
}

extern "C" void kernel_launch(void* const* d_in, const int* in_sizes, int n_in,
                              void* d_out, int out_size) {
    const float* prior = (const float*)d_in[0];
    const float* cam   = (const float*)d_in[1];
    const float* W1    = (const float*)d_in[2];
    const float* b1    = (const float*)d_in[3];
    const float* W2    = (const float*)d_in[4];
    const float* b2    = (const float*)d_in[5];
    const float* W3    = (const float*)d_in[6];
    const float* b3    = (const float*)d_in[7];
    float* out = (float*)d_out;

    dim3 grid((N_NET + GN - 1) / GN, B_TOT / ROWS);   // 181 x 64
    mlp_kernel<<<grid, 256>>>(prior, cam, W1, b1, W2, b2, W3, b3, out);
}